// round 16
// baseline (speedup 1.0000x reference)
#include <cuda_runtime.h>
#include <cuda_bf16.h>
#include <cstdint>

#define SQ     2048
#define DMODEL 1024
#define NHEAD  16
#define HDIM   64
#define WIN    256
#define BATCH  2
#define MROWS  (BATCH * SQ)      // 4096
#define KDIM   1024
#define NCHK   (KDIM / 64)       // 16 K-chunks of 64

// bf16 split operands (separate hi/lo, row-major [*, 1024])
__device__ __nv_bfloat16 g_aHi[MROWS * KDIM];
__device__ __nv_bfloat16 g_aLo[MROWS * KDIM];
__device__ __nv_bfloat16 g_w1Hi[3 * DMODEL * KDIM];
__device__ __nv_bfloat16 g_w1Lo[3 * DMODEL * KDIM];
__device__ __nv_bfloat16 g_w2Hi[DMODEL * KDIM];
__device__ __nv_bfloat16 g_w2Lo[DMODEL * KDIM];
// split qkv written by GEMM1 epilogue [MROWS, 3*DMODEL]
__device__ __nv_bfloat16 g_qkvHi[MROWS * 3 * DMODEL];
__device__ __nv_bfloat16 g_qkvLo[MROWS * 3 * DMODEL];

// ---------------------------------------------------------------------------
// PTX helpers (sm_80-level, compiles at compute_103)
// ---------------------------------------------------------------------------
__device__ __forceinline__ uint32_t smem_u32(const void* p) {
    uint32_t a;
    asm("{ .reg .u64 t; cvta.to.shared.u64 t, %1; cvt.u32.u64 %0, t; }" : "=r"(a) : "l"(p));
    return a;
}
#define CP_ASYNC16(dst, src) \
    asm volatile("cp.async.cg.shared.global [%0], [%1], 16;" :: "r"(dst), "l"(src))
#define CP_COMMIT()  asm volatile("cp.async.commit_group;" ::: "memory")
#define CP_WAIT0()   asm volatile("cp.async.wait_group 0;" ::: "memory")
#define CP_WAIT1()   asm volatile("cp.async.wait_group 1;" ::: "memory")

#define LDSM_X4(r, addr) \
    asm volatile("ldmatrix.sync.aligned.m8n8.x4.shared.b16 {%0,%1,%2,%3}, [%4];" \
        : "=r"((r)[0]), "=r"((r)[1]), "=r"((r)[2]), "=r"((r)[3]) : "r"(addr))
#define LDSM_X4_T(r, addr) \
    asm volatile("ldmatrix.sync.aligned.m8n8.x4.trans.shared.b16 {%0,%1,%2,%3}, [%4];" \
        : "=r"((r)[0]), "=r"((r)[1]), "=r"((r)[2]), "=r"((r)[3]) : "r"(addr))

#define MMA16816(c, a, b0, b1) \
    asm volatile("mma.sync.aligned.m16n8k16.row.col.f32.bf16.bf16.f32 " \
        "{%0,%1,%2,%3}, {%4,%5,%6,%7}, {%8,%9}, {%0,%1,%2,%3};" \
        : "+f"((c)[0]), "+f"((c)[1]), "+f"((c)[2]), "+f"((c)[3]) \
        : "r"((a)[0]), "r"((a)[1]), "r"((a)[2]), "r"((a)[3]), "r"(b0), "r"(b1))

// split (a,b) fp32 pair into packed bf16x2 hi and lo (low half = a)
__device__ __forceinline__ void split2(float a, float b, uint32_t& hi, uint32_t& lo) {
    __nv_bfloat162 h = __floats2bfloat162_rn(a, b);
    float2 hf = __bfloat1622float2(h);
    __nv_bfloat162 l = __floats2bfloat162_rn(a - hf.x, b - hf.y);
    hi = *reinterpret_cast<uint32_t*>(&h);
    lo = *reinterpret_cast<uint32_t*>(&l);
}

// ---------------------------------------------------------------------------
// conv_act: X[M,1024] fp32 -> hi/lo bf16 [M,1024] each (pass 1 only)
// ---------------------------------------------------------------------------
__global__ __launch_bounds__(256)
void conv_act_kernel(const float* __restrict__ X,
                     __nv_bfloat16* __restrict__ Hi, __nv_bfloat16* __restrict__ Lo)
{
    size_t t = (size_t)blockIdx.x * 256 + threadIdx.x;  // one float4 each
    size_t m = t >> 8;
    int k4 = (int)(t & 255) * 4;
    float4 x = *(const float4*)(X + m * KDIM + k4);
    uint32_t h0, l0, h1, l1;
    split2(x.x, x.y, h0, l0);
    split2(x.z, x.w, h1, l1);
    *(uint2*)(Hi + m * KDIM + k4) = make_uint2(h0, h1);
    *(uint2*)(Lo + m * KDIM + k4) = make_uint2(l0, l1);
}

// ---------------------------------------------------------------------------
// conv_w: W[1024,N] fp32 -> transposed hi/lo bf16 [N,1024]
// ---------------------------------------------------------------------------
__global__ __launch_bounds__(256)
void conv_w_kernel(const float* __restrict__ W,
                   __nv_bfloat16* __restrict__ Hi, __nv_bfloat16* __restrict__ Lo, int N)
{
    __shared__ float ts[32][33];
    int k0 = blockIdx.y * 32, n0 = blockIdx.x * 32;
    int tx = threadIdx.x, ty = threadIdx.y;   // (32, 8)
#pragma unroll
    for (int i = 0; i < 4; i++)
        ts[ty + i * 8][tx] = W[(size_t)(k0 + ty + i * 8) * N + n0 + tx];
    __syncthreads();
#pragma unroll
    for (int i = 0; i < 4; i++) {
        int n = n0 + ty + i * 8;
        int k = k0 + tx;
        float x = ts[tx][ty + i * 8];
        __nv_bfloat16 h = __float2bfloat16(x);
        __nv_bfloat16 l = __float2bfloat16(x - __bfloat162float(h));
        Hi[(size_t)n * KDIM + k] = h;
        Lo[(size_t)n * KDIM + k] = l;
    }
}

// ---------------------------------------------------------------------------
// 3-term bf16 mma.sync GEMM: C = (Ah+Al)(Bh+Bl)^T + bias  (drop Al*Bl)
// CTA tile 128x256, 256 threads (8 warps 2x4), warp tile 64x64.
// Epilogue writes fp32 C (if non-null) and/or split bf16 Chi/Clo (if non-null).
// ---------------------------------------------------------------------------
#define RSTR  144
#define AONE  (128 * RSTR)            // 18432 per A matrix
#define BONE  (256 * RSTR)            // 36864 per B matrix
#define BUFSZ (2 * AONE + 2 * BONE)   // 110592
#define GSMEM (2 * BUFSZ)             // 221184

__global__ __launch_bounds__(256, 1)
void gemm_mma_kernel(const __nv_bfloat16* __restrict__ Ah_g,
                     const __nv_bfloat16* __restrict__ Al_g,
                     const __nv_bfloat16* __restrict__ Bh_g,
                     const __nv_bfloat16* __restrict__ Bl_g,
                     const float* __restrict__ bias, float* __restrict__ C,
                     __nv_bfloat16* __restrict__ Chi, __nv_bfloat16* __restrict__ Clo,
                     int N)
{
    extern __shared__ char sm[];
    const uint32_t sb = smem_u32(sm);
    const int tid = threadIdx.x;
    const int lane = tid & 31, wid = tid >> 5;
    const int wm = wid & 1, wn = wid >> 1;          // 2 x 4 warps, tile 64x64
    const int m0 = blockIdx.y * 128, n0 = blockIdx.x * 256;

    const char* AgH = (const char*)(Ah_g + (size_t)m0 * KDIM);
    const char* AgL = (const char*)(Al_g + (size_t)m0 * KDIM);
    const char* BgH = (const char*)(Bh_g + (size_t)n0 * KDIM);
    const char* BgL = (const char*)(Bl_g + (size_t)n0 * KDIM);

    auto copy_chunk = [&](int c, int buf) {
        const uint32_t d = sb + buf * BUFSZ;
        const size_t kb = (size_t)c * 128;          // 64 bf16 = 128B
#pragma unroll
        for (int i = 0; i < 8; i++) {
            int u = tid + i * 256;                  // 0..2047
            int r = (u & 1023) >> 3, kc = u & 7;
            const char* src = (u < 1024) ? AgH : AgL;
            uint32_t dst = d + ((u < 1024) ? 0 : AONE) + r * RSTR + kc * 16;
            CP_ASYNC16(dst, src + (size_t)r * (KDIM * 2) + kb + kc * 16);
        }
#pragma unroll
        for (int i = 0; i < 16; i++) {
            int u = tid + i * 256;                  // 0..4095
            int r = (u & 2047) >> 3, kc = u & 7;
            const char* src = (u < 2048) ? BgH : BgL;
            uint32_t dst = d + 2 * AONE + ((u < 2048) ? 0 : BONE) + r * RSTR + kc * 16;
            CP_ASYNC16(dst, src + (size_t)r * (KDIM * 2) + kb + kc * 16);
        }
        CP_COMMIT();
    };

    float acc[4][8][4];
#pragma unroll
    for (int i = 0; i < 4; i++)
#pragma unroll
        for (int j = 0; j < 8; j++)
#pragma unroll
            for (int e = 0; e < 4; e++) acc[i][j][e] = 0.f;

    copy_chunk(0, 0);

    for (int c = 0; c < NCHK; c++) {
        const int buf = c & 1;
        if (c + 1 < NCHK) { copy_chunk(c + 1, 1 - buf); CP_WAIT1(); }
        else               CP_WAIT0();
        __syncthreads();

        const uint32_t AbH = sb + buf * BUFSZ;
        const uint32_t AbL = AbH + AONE;
        const uint32_t BbH = AbH + 2 * AONE;
        const uint32_t BbL = BbH + BONE;
#pragma unroll
        for (int s = 0; s < 4; s++) {
            const uint32_t koff = s * 32 + ((lane >> 4) & 1) * 16;
            const uint32_t koffB = s * 32 + ((lane >> 3) & 1) * 16;
            uint32_t Bh[4][4], Bl[4][4];
#pragma unroll
            for (int g = 0; g < 4; g++) {
                int n = wn * 64 + g * 16 + (lane & 7) + ((lane >> 4) & 1) * 8;
                LDSM_X4(Bh[g], BbH + n * RSTR + koffB);
                LDSM_X4(Bl[g], BbL + n * RSTR + koffB);
            }
#pragma unroll
            for (int mi = 0; mi < 4; mi++) {
                int r = wm * 64 + mi * 16 + (lane & 15);
                uint32_t Aa[4];
                LDSM_X4(Aa, AbH + r * RSTR + koff);     // A hi
#pragma unroll
                for (int nj = 0; nj < 8; nj++) {        // hh
                    uint32_t* Bf = Bh[nj >> 1];
                    MMA16816(acc[mi][nj], Aa, Bf[(nj & 1) * 2], Bf[(nj & 1) * 2 + 1]);
                }
#pragma unroll
                for (int nj = 0; nj < 8; nj++) {        // hl
                    uint32_t* Bf = Bl[nj >> 1];
                    MMA16816(acc[mi][nj], Aa, Bf[(nj & 1) * 2], Bf[(nj & 1) * 2 + 1]);
                }
                LDSM_X4(Aa, AbL + r * RSTR + koff);     // A lo
#pragma unroll
                for (int nj = 0; nj < 8; nj++) {        // lh
                    uint32_t* Bf = Bh[nj >> 1];
                    MMA16816(acc[mi][nj], Aa, Bf[(nj & 1) * 2], Bf[(nj & 1) * 2 + 1]);
                }
            }
        }
        __syncthreads();
    }

    // Epilogue
    const int gr = lane >> 2, gc = (lane & 3) * 2;
#pragma unroll
    for (int mi = 0; mi < 4; mi++) {
#pragma unroll
        for (int nj = 0; nj < 8; nj++) {
            int row = m0 + wm * 64 + mi * 16 + gr;
            int col = n0 + wn * 64 + nj * 8 + gc;
            float b0v = bias[col], b1v = bias[col + 1];
            float v0 = acc[mi][nj][0] + b0v, v1 = acc[mi][nj][1] + b1v;
            float v2 = acc[mi][nj][2] + b0v, v3 = acc[mi][nj][3] + b1v;
            if (C) {
                *(float2*)(&C[(size_t)row * N + col]) = make_float2(v0, v1);
                *(float2*)(&C[(size_t)(row + 8) * N + col]) = make_float2(v2, v3);
            }
            if (Chi) {
                uint32_t h, l;
                split2(v0, v1, h, l);
                *(uint32_t*)(Chi + (size_t)row * N + col) = h;
                *(uint32_t*)(Clo + (size_t)row * N + col) = l;
                split2(v2, v3, h, l);
                *(uint32_t*)(Chi + (size_t)(row + 8) * N + col) = h;
                *(uint32_t*)(Clo + (size_t)(row + 8) * N + col) = l;
            }
        }
    }
}

// ---------------------------------------------------------------------------
// Tensor-core local-causal flash attention, v2:
//  - Q fragments hoisted out of the key-tile loop (Q invariant)
//  - K double-buffered: K(kt+1) cp.async overlaps softmax+PV of kt
//  - V single-buffered: V(kt+1) cp.async overlaps S of kt+1
// Grid (SQ/64, H, B), 128 threads (4 warps), warp = 16 q-rows x 64 keys.
// ---------------------------------------------------------------------------
#define ARS   144
#define ATILE (64 * ARS)              // 9216
// layout: Qh Ql | Kh0 Kl0 | Kh1 Kl1 | Vh Vl
#define ASMEM (8 * ATILE)             // 73728

__global__ __launch_bounds__(128, 3)
void attn_mma_kernel(const __nv_bfloat16* __restrict__ qkvHi,
                     const __nv_bfloat16* __restrict__ qkvLo,
                     __nv_bfloat16* __restrict__ mixHi,
                     __nv_bfloat16* __restrict__ mixLo)
{
    extern __shared__ char smc[];
    const uint32_t sb = smem_u32(smc);
    const uint32_t sQh = sb, sQl = sb + ATILE;
    const uint32_t sKh[2] = {sb + 2 * ATILE, sb + 4 * ATILE};
    const uint32_t sKl[2] = {sb + 3 * ATILE, sb + 5 * ATILE};
    const uint32_t sVh = sb + 6 * ATILE, sVl = sb + 7 * ATILE;

    const int qb = blockIdx.x, h = blockIdx.y, b = blockIdx.z;
    const int tid = threadIdx.x, lane = tid & 31, w = tid >> 5;
    const int q0 = qb * 64;
    const int gr = lane >> 2;
    const int gc2 = (lane & 3) * 2;

    const size_t rs = 3 * DMODEL;
    const __nv_bfloat16* qkH = qkvHi + (size_t)b * SQ * rs + h * HDIM;
    const __nv_bfloat16* qkL = qkvLo + (size_t)b * SQ * rs + h * HDIM;

    // 1024 16B-units per (hi+lo) 64-row tile pair -> 8 iters x 128 threads
    auto load_k = [&](int kt, int buf) {
        int k0 = kt * 64;
#pragma unroll
        for (int i = 0; i < 8; i++) {
            int u = tid + i * 128;
            int r = (u >> 3) & 63, un = u & 7;
            const __nv_bfloat16* src = ((u < 512) ? qkH : qkL) + DMODEL;
            uint32_t dst = ((u < 512) ? sKh[buf] : sKl[buf]) + r * ARS + un * 16;
            CP_ASYNC16(dst, (const char*)(src + (size_t)(k0 + r) * rs) + un * 16);
        }
        CP_COMMIT();
    };
    auto load_v = [&](int kt) {
        int k0 = kt * 64;
#pragma unroll
        for (int i = 0; i < 8; i++) {
            int u = tid + i * 128;
            int r = (u >> 3) & 63, un = u & 7;
            const __nv_bfloat16* src = ((u < 512) ? qkH : qkL) + 2 * DMODEL;
            uint32_t dst = ((u < 512) ? sVh : sVl) + r * ARS + un * 16;
            CP_ASYNC16(dst, (const char*)(src + (size_t)(k0 + r) * rs) + un * 16);
        }
        CP_COMMIT();
    };

    const int kt0 = (qb >= 4) ? (qb - 4) : 0;

    // Prologue: Q + K(kt0) (group), V(kt0) (group); wait all.
    {
#pragma unroll
        for (int i = 0; i < 8; i++) {
            int u = tid + i * 128;
            int r = (u >> 3) & 63, un = u & 7;
            const __nv_bfloat16* src = (u < 512) ? qkH : qkL;
            uint32_t dst = ((u < 512) ? sQh : sQl) + r * ARS + un * 16;
            CP_ASYNC16(dst, (const char*)(src + (size_t)(q0 + r) * rs) + un * 16);
        }
    }
    load_k(kt0, 0);     // commits Q+K0 together
    load_v(kt0);        // commits V0
    CP_WAIT0();
    __syncthreads();

    // Hoist Q fragments (invariant across key tiles)
    uint32_t Qh_f[4][4], Ql_f[4][4];
    {
        int r = w * 16 + (lane & 15);
#pragma unroll
        for (int s = 0; s < 4; s++) {
            uint32_t koff = s * 32 + ((lane >> 4) & 1) * 16;
            LDSM_X4(Qh_f[s], sQh + r * ARS + koff);
            LDSM_X4(Ql_f[s], sQl + r * ARS + koff);
        }
    }

    float m0_ = -1e30f, m1_ = -1e30f, l0 = 0.f, l1 = 0.f;
    float O[8][4];
#pragma unroll
    for (int j = 0; j < 8; j++)
#pragma unroll
        for (int e = 0; e < 4; e++) O[j][e] = 0.f;

    for (int kt = kt0; kt <= qb; kt++) {
        const int k0 = kt * 64;
        const int cur = (kt - kt0) & 1;

        // ---- S = Q @ K^T (3-term) ----
        float sS[8][4];
#pragma unroll
        for (int j = 0; j < 8; j++)
#pragma unroll
            for (int e = 0; e < 4; e++) sS[j][e] = 0.f;

#pragma unroll
        for (int s = 0; s < 4; s++) {
            uint32_t Bh4[4][4], Bl4[4][4];
            {
                int n = (lane & 7) + ((lane >> 4) & 1) * 8;
                uint32_t koffB = s * 32 + ((lane >> 3) & 1) * 16;
#pragma unroll
                for (int g = 0; g < 4; g++) {
                    LDSM_X4(Bh4[g], sKh[cur] + (g * 16 + n) * ARS + koffB);
                    LDSM_X4(Bl4[g], sKl[cur] + (g * 16 + n) * ARS + koffB);
                }
            }
#pragma unroll
            for (int j = 0; j < 8; j++) {
                uint32_t b0h = Bh4[j >> 1][(j & 1) * 2], b1h = Bh4[j >> 1][(j & 1) * 2 + 1];
                uint32_t b0l = Bl4[j >> 1][(j & 1) * 2], b1l = Bl4[j >> 1][(j & 1) * 2 + 1];
                MMA16816(sS[j], Qh_f[s], b0h, b1h);
                MMA16816(sS[j], Qh_f[s], b0l, b1l);
                MMA16816(sS[j], Ql_f[s], b0h, b1h);
            }
        }

        // All warps done reading K[cur] -> start K(kt+1) into the other buffer.
        __syncthreads();
        if (kt < qb) load_k(kt + 1, 1 - cur);

        // ---- mask + scale ----
        const int qrow0 = q0 + w * 16 + gr;
#pragma unroll
        for (int j = 0; j < 8; j++) {
#pragma unroll
            for (int e = 0; e < 4; e++) {
                int kg = k0 + j * 8 + gc2 + (e & 1);
                int qg = qrow0 + (e >> 1) * 8;
                bool ok = (kg <= qg) && (kg + WIN > qg);
                sS[j][e] = ok ? sS[j][e] * 0.125f : -1e30f;
            }
        }
        // ---- online softmax (register-local) ----
        float rmax0 = -1e30f, rmax1 = -1e30f;
#pragma unroll
        for (int j = 0; j < 8; j++) {
            rmax0 = fmaxf(rmax0, fmaxf(sS[j][0], sS[j][1]));
            rmax1 = fmaxf(rmax1, fmaxf(sS[j][2], sS[j][3]));
        }
        rmax0 = fmaxf(rmax0, __shfl_xor_sync(0xffffffffu, rmax0, 1));
        rmax0 = fmaxf(rmax0, __shfl_xor_sync(0xffffffffu, rmax0, 2));
        rmax1 = fmaxf(rmax1, __shfl_xor_sync(0xffffffffu, rmax1, 1));
        rmax1 = fmaxf(rmax1, __shfl_xor_sync(0xffffffffu, rmax1, 2));
        const float mn0 = fmaxf(m0_, rmax0), mn1 = fmaxf(m1_, rmax1);
        const float al0 = __expf(m0_ - mn0), al1 = __expf(m1_ - mn1);
        float ps0 = 0.f, ps1 = 0.f;
#pragma unroll
        for (int j = 0; j < 8; j++) {
            float p0 = (sS[j][0] > -1e29f) ? __expf(sS[j][0] - mn0) : 0.f;
            float p1 = (sS[j][1] > -1e29f) ? __expf(sS[j][1] - mn0) : 0.f;
            float p2 = (sS[j][2] > -1e29f) ? __expf(sS[j][2] - mn1) : 0.f;
            float p3 = (sS[j][3] > -1e29f) ? __expf(sS[j][3] - mn1) : 0.f;
            ps0 += p0 + p1; ps1 += p2 + p3;
            sS[j][0] = p0; sS[j][1] = p1; sS[j][2] = p2; sS[j][3] = p3;
        }
        ps0 += __shfl_xor_sync(0xffffffffu, ps0, 1);
        ps0 += __shfl_xor_sync(0xffffffffu, ps0, 2);
        ps1 += __shfl_xor_sync(0xffffffffu, ps1, 1);
        ps1 += __shfl_xor_sync(0xffffffffu, ps1, 2);
        l0 = l0 * al0 + ps0;
        l1 = l1 * al1 + ps1;
        m0_ = mn0; m1_ = mn1;
#pragma unroll
        for (int j = 0; j < 8; j++) {
            O[j][0] *= al0; O[j][1] *= al0;
            O[j][2] *= al1; O[j][3] *= al1;
        }

        // V(kt) must be resident (pending groups: [V(kt)?, K(kt+1)])
        if (kt < qb) CP_WAIT1(); else CP_WAIT0();
        __syncthreads();

        // ---- O += P @ V (3-term) ----
#pragma unroll
        for (int s = 0; s < 4; s++) {
            uint32_t pah[4], pal[4];
            split2(sS[2 * s][0], sS[2 * s][1], pah[0], pal[0]);
            split2(sS[2 * s][2], sS[2 * s][3], pah[1], pal[1]);
            split2(sS[2 * s + 1][0], sS[2 * s + 1][1], pah[2], pal[2]);
            split2(sS[2 * s + 1][2], sS[2 * s + 1][3], pah[3], pal[3]);

            uint32_t Vh4[4][4], Vl4[4][4];
            {
                int ksr = s * 16 + (lane & 7) + ((lane >> 3) & 1) * 8;
                uint32_t dby = ((lane >> 4) & 1) * 16;
#pragma unroll
                for (int dt = 0; dt < 4; dt++) {
                    LDSM_X4_T(Vh4[dt], sVh + ksr * ARS + dt * 32 + dby);
                    LDSM_X4_T(Vl4[dt], sVl + ksr * ARS + dt * 32 + dby);
                }
            }
#pragma unroll
            for (int j = 0; j < 8; j++) {
                uint32_t b0h = Vh4[j >> 1][(j & 1) * 2], b1h = Vh4[j >> 1][(j & 1) * 2 + 1];
                uint32_t b0l = Vl4[j >> 1][(j & 1) * 2], b1l = Vl4[j >> 1][(j & 1) * 2 + 1];
                MMA16816(O[j], pah, b0h, b1h);
                MMA16816(O[j], pah, b0l, b1l);
                MMA16816(O[j], pal, b0h, b1h);
            }
        }

        if (kt < qb) {
            __syncthreads();            // all warps done reading V(kt)
            load_v(kt + 1);             // overlaps next tile's S
            CP_WAIT1();                 // K(kt+1) done (older group)
            __syncthreads();
        }
    }

    // ---- finalize: write split bf16 mixed [MROWS, DMODEL] ----
    const float i0 = 1.f / l0, i1 = 1.f / l1;
    const size_t row0 = (size_t)b * SQ + q0 + w * 16 + gr;
    const int colb = h * HDIM + gc2;
#pragma unroll
    for (int j = 0; j < 8; j++) {
        uint32_t hh, ll;
        split2(O[j][0] * i0, O[j][1] * i0, hh, ll);
        *(uint32_t*)(mixHi + row0 * DMODEL + colb + j * 8) = hh;
        *(uint32_t*)(mixLo + row0 * DMODEL + colb + j * 8) = ll;
        split2(O[j][2] * i1, O[j][3] * i1, hh, ll);
        *(uint32_t*)(mixHi + (row0 + 8) * DMODEL + colb + j * 8) = hh;
        *(uint32_t*)(mixLo + (row0 + 8) * DMODEL + colb + j * 8) = ll;
    }
}

// ---------------------------------------------------------------------------
extern "C" void kernel_launch(void* const* d_in, const int* in_sizes, int n_in,
                              void* d_out, int out_size)
{
    const float* normed = (const float*)d_in[0];
    // d_in[1] = attn_mask: analytic (k<=q && k>=q-255), unused
    const float* Wqkv = (const float*)d_in[2];
    const float* bqkv = (const float*)d_in[3];
    const float* Wout = (const float*)d_in[4];
    const float* bout = (const float*)d_in[5];
    float* out = (float*)d_out;

    __nv_bfloat16 *aHi, *aLo, *w1Hi, *w1Lo, *w2Hi, *w2Lo, *qkvHi, *qkvLo;
    cudaGetSymbolAddress((void**)&aHi, g_aHi);
    cudaGetSymbolAddress((void**)&aLo, g_aLo);
    cudaGetSymbolAddress((void**)&w1Hi, g_w1Hi);
    cudaGetSymbolAddress((void**)&w1Lo, g_w1Lo);
    cudaGetSymbolAddress((void**)&w2Hi, g_w2Hi);
    cudaGetSymbolAddress((void**)&w2Lo, g_w2Lo);
    cudaGetSymbolAddress((void**)&qkvHi, g_qkvHi);
    cudaGetSymbolAddress((void**)&qkvLo, g_qkvLo);

    cudaFuncSetAttribute(gemm_mma_kernel,
                         cudaFuncAttributeMaxDynamicSharedMemorySize, GSMEM);
    cudaFuncSetAttribute(attn_mma_kernel,
                         cudaFuncAttributeMaxDynamicSharedMemorySize, ASMEM);

    // 1) split/convert normed + Wqkv
    conv_act_kernel<<<MROWS, 256>>>(normed, aHi, aLo);
    conv_w_kernel<<<dim3(3 * DMODEL / 32, KDIM / 32), dim3(32, 8)>>>(Wqkv, w1Hi, w1Lo, 3 * DMODEL);

    // 2) qkv GEMM -> split bf16 qkv directly
    gemm_mma_kernel<<<dim3(3 * DMODEL / 256, MROWS / 128), 256, GSMEM>>>(
        aHi, aLo, w1Hi, w1Lo, bqkv, nullptr, qkvHi, qkvLo, 3 * DMODEL);

    // 3) tensor-core local attention -> split bf16 mixed (into aHi/aLo)
    dim3 g2(SQ / 64, NHEAD, BATCH);
    attn_mma_kernel<<<g2, 128, ASMEM>>>(qkvHi, qkvLo, aHi, aLo);

    // 4) Wout conversion + out GEMM (fp32 out)
    conv_w_kernel<<<dim3(DMODEL / 32, KDIM / 32), dim3(32, 8)>>>(Wout, w2Hi, w2Lo, DMODEL);
    gemm_mma_kernel<<<dim3(DMODEL / 256, MROWS / 128), 256, GSMEM>>>(
        aHi, aLo, w2Hi, w2Lo, bout, out, nullptr, nullptr, DMODEL);
}

// round 17
// speedup vs baseline: 1.4934x; 1.4934x over previous
#include <cuda_runtime.h>
#include <cuda_bf16.h>
#include <cstdint>

#define SQ     2048
#define DMODEL 1024
#define NHEAD  16
#define HDIM   64
#define WIN    256
#define BATCH  2
#define MROWS  (BATCH * SQ)      // 4096
#define KDIM   1024
#define NCHK   (KDIM / 64)       // 16 K-chunks of 64

// bf16 split operands (separate hi/lo, row-major [*, 1024])
__device__ __nv_bfloat16 g_aHi[MROWS * KDIM];
__device__ __nv_bfloat16 g_aLo[MROWS * KDIM];
__device__ __nv_bfloat16 g_w1Hi[3 * DMODEL * KDIM];
__device__ __nv_bfloat16 g_w1Lo[3 * DMODEL * KDIM];
__device__ __nv_bfloat16 g_w2Hi[DMODEL * KDIM];
__device__ __nv_bfloat16 g_w2Lo[DMODEL * KDIM];
// split qkv written by GEMM1 epilogue [MROWS, 3*DMODEL]
__device__ __nv_bfloat16 g_qkvHi[MROWS * 3 * DMODEL];
__device__ __nv_bfloat16 g_qkvLo[MROWS * 3 * DMODEL];

// ---------------------------------------------------------------------------
// PTX helpers (sm_80-level, compiles at compute_103)
// ---------------------------------------------------------------------------
__device__ __forceinline__ uint32_t smem_u32(const void* p) {
    uint32_t a;
    asm("{ .reg .u64 t; cvta.to.shared.u64 t, %1; cvt.u32.u64 %0, t; }" : "=r"(a) : "l"(p));
    return a;
}
#define CP_ASYNC16(dst, src) \
    asm volatile("cp.async.cg.shared.global [%0], [%1], 16;" :: "r"(dst), "l"(src))
#define CP_COMMIT()  asm volatile("cp.async.commit_group;" ::: "memory")
#define CP_WAIT0()   asm volatile("cp.async.wait_group 0;" ::: "memory")
#define CP_WAIT1()   asm volatile("cp.async.wait_group 1;" ::: "memory")

#define LDSM_X4(r, addr) \
    asm volatile("ldmatrix.sync.aligned.m8n8.x4.shared.b16 {%0,%1,%2,%3}, [%4];" \
        : "=r"((r)[0]), "=r"((r)[1]), "=r"((r)[2]), "=r"((r)[3]) : "r"(addr))
#define LDSM_X4_T(r, addr) \
    asm volatile("ldmatrix.sync.aligned.m8n8.x4.trans.shared.b16 {%0,%1,%2,%3}, [%4];" \
        : "=r"((r)[0]), "=r"((r)[1]), "=r"((r)[2]), "=r"((r)[3]) : "r"(addr))

#define MMA16816(c, a, b0, b1) \
    asm volatile("mma.sync.aligned.m16n8k16.row.col.f32.bf16.bf16.f32 " \
        "{%0,%1,%2,%3}, {%4,%5,%6,%7}, {%8,%9}, {%0,%1,%2,%3};" \
        : "+f"((c)[0]), "+f"((c)[1]), "+f"((c)[2]), "+f"((c)[3]) \
        : "r"((a)[0]), "r"((a)[1]), "r"((a)[2]), "r"((a)[3]), "r"(b0), "r"(b1))

// split (a,b) fp32 pair into packed bf16x2 hi and lo (low half = a)
__device__ __forceinline__ void split2(float a, float b, uint32_t& hi, uint32_t& lo) {
    __nv_bfloat162 h = __floats2bfloat162_rn(a, b);
    float2 hf = __bfloat1622float2(h);
    __nv_bfloat162 l = __floats2bfloat162_rn(a - hf.x, b - hf.y);
    hi = *reinterpret_cast<uint32_t*>(&h);
    lo = *reinterpret_cast<uint32_t*>(&l);
}

// ---------------------------------------------------------------------------
// conv_act: X[M,1024] fp32 -> hi/lo bf16 [M,1024] each (pass 1 only)
// ---------------------------------------------------------------------------
__global__ __launch_bounds__(256)
void conv_act_kernel(const float* __restrict__ X,
                     __nv_bfloat16* __restrict__ Hi, __nv_bfloat16* __restrict__ Lo)
{
    size_t t = (size_t)blockIdx.x * 256 + threadIdx.x;  // one float4 each
    size_t m = t >> 8;
    int k4 = (int)(t & 255) * 4;
    float4 x = *(const float4*)(X + m * KDIM + k4);
    uint32_t h0, l0, h1, l1;
    split2(x.x, x.y, h0, l0);
    split2(x.z, x.w, h1, l1);
    *(uint2*)(Hi + m * KDIM + k4) = make_uint2(h0, h1);
    *(uint2*)(Lo + m * KDIM + k4) = make_uint2(l0, l1);
}

// ---------------------------------------------------------------------------
// conv_w: W[1024,N] fp32 -> transposed hi/lo bf16 [N,1024]
// ---------------------------------------------------------------------------
__global__ __launch_bounds__(256)
void conv_w_kernel(const float* __restrict__ W,
                   __nv_bfloat16* __restrict__ Hi, __nv_bfloat16* __restrict__ Lo, int N)
{
    __shared__ float ts[32][33];
    int k0 = blockIdx.y * 32, n0 = blockIdx.x * 32;
    int tx = threadIdx.x, ty = threadIdx.y;   // (32, 8)
#pragma unroll
    for (int i = 0; i < 4; i++)
        ts[ty + i * 8][tx] = W[(size_t)(k0 + ty + i * 8) * N + n0 + tx];
    __syncthreads();
#pragma unroll
    for (int i = 0; i < 4; i++) {
        int n = n0 + ty + i * 8;
        int k = k0 + tx;
        float x = ts[tx][ty + i * 8];
        __nv_bfloat16 h = __float2bfloat16(x);
        __nv_bfloat16 l = __float2bfloat16(x - __bfloat162float(h));
        Hi[(size_t)n * KDIM + k] = h;
        Lo[(size_t)n * KDIM + k] = l;
    }
}

// ---------------------------------------------------------------------------
// 3-term bf16 mma.sync GEMM: C = (Ah+Al)(Bh+Bl)^T + bias  (drop Al*Bl)
// CTA tile 128x256, 256 threads (8 warps 2x4), warp tile 64x64.
// Epilogue writes fp32 C (if non-null) and/or split bf16 Chi/Clo (if non-null).
// ---------------------------------------------------------------------------
#define RSTR  144
#define AONE  (128 * RSTR)            // 18432 per A matrix
#define BONE  (256 * RSTR)            // 36864 per B matrix
#define BUFSZ (2 * AONE + 2 * BONE)   // 110592
#define GSMEM (2 * BUFSZ)             // 221184

__global__ __launch_bounds__(256, 1)
void gemm_mma_kernel(const __nv_bfloat16* __restrict__ Ah_g,
                     const __nv_bfloat16* __restrict__ Al_g,
                     const __nv_bfloat16* __restrict__ Bh_g,
                     const __nv_bfloat16* __restrict__ Bl_g,
                     const float* __restrict__ bias, float* __restrict__ C,
                     __nv_bfloat16* __restrict__ Chi, __nv_bfloat16* __restrict__ Clo,
                     int N)
{
    extern __shared__ char sm[];
    const uint32_t sb = smem_u32(sm);
    const int tid = threadIdx.x;
    const int lane = tid & 31, wid = tid >> 5;
    const int wm = wid & 1, wn = wid >> 1;          // 2 x 4 warps, tile 64x64
    const int m0 = blockIdx.y * 128, n0 = blockIdx.x * 256;

    const char* AgH = (const char*)(Ah_g + (size_t)m0 * KDIM);
    const char* AgL = (const char*)(Al_g + (size_t)m0 * KDIM);
    const char* BgH = (const char*)(Bh_g + (size_t)n0 * KDIM);
    const char* BgL = (const char*)(Bl_g + (size_t)n0 * KDIM);

    auto copy_chunk = [&](int c, int buf) {
        const uint32_t d = sb + buf * BUFSZ;
        const size_t kb = (size_t)c * 128;          // 64 bf16 = 128B
#pragma unroll
        for (int i = 0; i < 8; i++) {
            int u = tid + i * 256;                  // 0..2047
            int r = (u & 1023) >> 3, kc = u & 7;
            const char* src = (u < 1024) ? AgH : AgL;
            uint32_t dst = d + ((u < 1024) ? 0 : AONE) + r * RSTR + kc * 16;
            CP_ASYNC16(dst, src + (size_t)r * (KDIM * 2) + kb + kc * 16);
        }
#pragma unroll
        for (int i = 0; i < 16; i++) {
            int u = tid + i * 256;                  // 0..4095
            int r = (u & 2047) >> 3, kc = u & 7;
            const char* src = (u < 2048) ? BgH : BgL;
            uint32_t dst = d + 2 * AONE + ((u < 2048) ? 0 : BONE) + r * RSTR + kc * 16;
            CP_ASYNC16(dst, src + (size_t)r * (KDIM * 2) + kb + kc * 16);
        }
        CP_COMMIT();
    };

    float acc[4][8][4];
#pragma unroll
    for (int i = 0; i < 4; i++)
#pragma unroll
        for (int j = 0; j < 8; j++)
#pragma unroll
            for (int e = 0; e < 4; e++) acc[i][j][e] = 0.f;

    copy_chunk(0, 0);

    for (int c = 0; c < NCHK; c++) {
        const int buf = c & 1;
        if (c + 1 < NCHK) { copy_chunk(c + 1, 1 - buf); CP_WAIT1(); }
        else               CP_WAIT0();
        __syncthreads();

        const uint32_t AbH = sb + buf * BUFSZ;
        const uint32_t AbL = AbH + AONE;
        const uint32_t BbH = AbH + 2 * AONE;
        const uint32_t BbL = BbH + BONE;
#pragma unroll
        for (int s = 0; s < 4; s++) {
            const uint32_t koff = s * 32 + ((lane >> 4) & 1) * 16;
            const uint32_t koffB = s * 32 + ((lane >> 3) & 1) * 16;
            uint32_t Bh[4][4], Bl[4][4];
#pragma unroll
            for (int g = 0; g < 4; g++) {
                int n = wn * 64 + g * 16 + (lane & 7) + ((lane >> 4) & 1) * 8;
                LDSM_X4(Bh[g], BbH + n * RSTR + koffB);
                LDSM_X4(Bl[g], BbL + n * RSTR + koffB);
            }
#pragma unroll
            for (int mi = 0; mi < 4; mi++) {
                int r = wm * 64 + mi * 16 + (lane & 15);
                uint32_t Aa[4];
                LDSM_X4(Aa, AbH + r * RSTR + koff);     // A hi
#pragma unroll
                for (int nj = 0; nj < 8; nj++) {        // hh
                    uint32_t* Bf = Bh[nj >> 1];
                    MMA16816(acc[mi][nj], Aa, Bf[(nj & 1) * 2], Bf[(nj & 1) * 2 + 1]);
                }
#pragma unroll
                for (int nj = 0; nj < 8; nj++) {        // hl
                    uint32_t* Bf = Bl[nj >> 1];
                    MMA16816(acc[mi][nj], Aa, Bf[(nj & 1) * 2], Bf[(nj & 1) * 2 + 1]);
                }
                LDSM_X4(Aa, AbL + r * RSTR + koff);     // A lo
#pragma unroll
                for (int nj = 0; nj < 8; nj++) {        // lh
                    uint32_t* Bf = Bh[nj >> 1];
                    MMA16816(acc[mi][nj], Aa, Bf[(nj & 1) * 2], Bf[(nj & 1) * 2 + 1]);
                }
            }
        }
        __syncthreads();
    }

    // Epilogue
    const int gr = lane >> 2, gc = (lane & 3) * 2;
#pragma unroll
    for (int mi = 0; mi < 4; mi++) {
#pragma unroll
        for (int nj = 0; nj < 8; nj++) {
            int row = m0 + wm * 64 + mi * 16 + gr;
            int col = n0 + wn * 64 + nj * 8 + gc;
            float b0v = bias[col], b1v = bias[col + 1];
            float v0 = acc[mi][nj][0] + b0v, v1 = acc[mi][nj][1] + b1v;
            float v2 = acc[mi][nj][2] + b0v, v3 = acc[mi][nj][3] + b1v;
            if (C) {
                *(float2*)(&C[(size_t)row * N + col]) = make_float2(v0, v1);
                *(float2*)(&C[(size_t)(row + 8) * N + col]) = make_float2(v2, v3);
            }
            if (Chi) {
                uint32_t h, l;
                split2(v0, v1, h, l);
                *(uint32_t*)(Chi + (size_t)row * N + col) = h;
                *(uint32_t*)(Clo + (size_t)row * N + col) = l;
                split2(v2, v3, h, l);
                *(uint32_t*)(Chi + (size_t)(row + 8) * N + col) = h;
                *(uint32_t*)(Clo + (size_t)(row + 8) * N + col) = l;
            }
        }
    }
}

// ---------------------------------------------------------------------------
// Tensor-core local-causal flash attention (R15 structure; V double-buffered).
// Per key tile: S (reads K) -> sync -> issue K(kt+1)+V(kt+1,alt) loads ->
// softmax + PV (reads V[cur]) -> CP_WAIT0 -> sync.  Loads overlap softmax+PV.
// Grid (SQ/64, H, B), 128 threads (4 warps), warp = 16 q-rows x 64 keys.
// ---------------------------------------------------------------------------
#define ARS   144
#define ATILE (64 * ARS)              // 9216
// layout: Qh Ql | Kh Kl | Vh0 Vl0 | Vh1 Vl1
#define ASMEM (8 * ATILE)             // 73728

__global__ __launch_bounds__(128)
void attn_mma_kernel(const __nv_bfloat16* __restrict__ qkvHi,
                     const __nv_bfloat16* __restrict__ qkvLo,
                     __nv_bfloat16* __restrict__ mixHi,
                     __nv_bfloat16* __restrict__ mixLo)
{
    extern __shared__ char smc[];
    const uint32_t sb = smem_u32(smc);
    const uint32_t sQh = sb, sQl = sb + ATILE;
    const uint32_t sKh = sb + 2 * ATILE, sKl = sb + 3 * ATILE;
    const uint32_t sVh[2] = {sb + 4 * ATILE, sb + 6 * ATILE};
    const uint32_t sVl[2] = {sb + 5 * ATILE, sb + 7 * ATILE};

    const int qb = blockIdx.x, h = blockIdx.y, b = blockIdx.z;
    const int tid = threadIdx.x, lane = tid & 31, w = tid >> 5;
    const int q0 = qb * 64;
    const int gr = lane >> 2;
    const int gc2 = (lane & 3) * 2;

    const size_t rs = 3 * DMODEL;
    const __nv_bfloat16* qkH = qkvHi + (size_t)b * SQ * rs + h * HDIM;
    const __nv_bfloat16* qkL = qkvLo + (size_t)b * SQ * rs + h * HDIM;

    // one (hi+lo) 64-row tile pair = 1024 16B-units -> 8 iters x 128 threads
    auto load_k = [&](int kt) {
        int k0 = kt * 64;
#pragma unroll
        for (int i = 0; i < 8; i++) {
            int u = tid + i * 128;
            int r = (u >> 3) & 63, un = u & 7;
            const __nv_bfloat16* src = ((u < 512) ? qkH : qkL) + DMODEL;
            uint32_t dst = ((u < 512) ? sKh : sKl) + r * ARS + un * 16;
            CP_ASYNC16(dst, (const char*)(src + (size_t)(k0 + r) * rs) + un * 16);
        }
    };
    auto load_v = [&](int kt, int vb) {
        int k0 = kt * 64;
#pragma unroll
        for (int i = 0; i < 8; i++) {
            int u = tid + i * 128;
            int r = (u >> 3) & 63, un = u & 7;
            const __nv_bfloat16* src = ((u < 512) ? qkH : qkL) + 2 * DMODEL;
            uint32_t dst = ((u < 512) ? sVh[vb] : sVl[vb]) + r * ARS + un * 16;
            CP_ASYNC16(dst, (const char*)(src + (size_t)(k0 + r) * rs) + un * 16);
        }
    };

    const int kt0 = (qb >= 4) ? (qb - 4) : 0;

    // Prologue: Q + K(kt0) + V(kt0) in one group; wait all.
    {
#pragma unroll
        for (int i = 0; i < 8; i++) {
            int u = tid + i * 128;
            int r = (u >> 3) & 63, un = u & 7;
            const __nv_bfloat16* src = (u < 512) ? qkH : qkL;
            uint32_t dst = ((u < 512) ? sQh : sQl) + r * ARS + un * 16;
            CP_ASYNC16(dst, (const char*)(src + (size_t)(q0 + r) * rs) + un * 16);
        }
    }
    load_k(kt0);
    load_v(kt0, 0);
    CP_COMMIT();
    CP_WAIT0();
    __syncthreads();

    float m0_ = -1e30f, m1_ = -1e30f, l0 = 0.f, l1 = 0.f;
    float O[8][4];
#pragma unroll
    for (int j = 0; j < 8; j++)
#pragma unroll
        for (int e = 0; e < 4; e++) O[j][e] = 0.f;

    for (int kt = kt0; kt <= qb; kt++) {
        const int k0 = kt * 64;
        const int vb = (kt - kt0) & 1;

        // ---- S = Q @ K^T (3-term) ----
        float sS[8][4];
#pragma unroll
        for (int j = 0; j < 8; j++)
#pragma unroll
            for (int e = 0; e < 4; e++) sS[j][e] = 0.f;

#pragma unroll
        for (int s = 0; s < 4; s++) {
            uint32_t Aq[4], Alr[4];
            {
                int r = w * 16 + (lane & 15);
                uint32_t koff = s * 32 + ((lane >> 4) & 1) * 16;
                LDSM_X4(Aq, sQh + r * ARS + koff);
                LDSM_X4(Alr, sQl + r * ARS + koff);
            }
            uint32_t Bh4[4][4], Bl4[4][4];
            {
                int n = (lane & 7) + ((lane >> 4) & 1) * 8;
                uint32_t koffB = s * 32 + ((lane >> 3) & 1) * 16;
#pragma unroll
                for (int g = 0; g < 4; g++) {
                    LDSM_X4(Bh4[g], sKh + (g * 16 + n) * ARS + koffB);
                    LDSM_X4(Bl4[g], sKl + (g * 16 + n) * ARS + koffB);
                }
            }
#pragma unroll
            for (int j = 0; j < 8; j++) {
                uint32_t b0h = Bh4[j >> 1][(j & 1) * 2], b1h = Bh4[j >> 1][(j & 1) * 2 + 1];
                uint32_t b0l = Bl4[j >> 1][(j & 1) * 2], b1l = Bl4[j >> 1][(j & 1) * 2 + 1];
                MMA16816(sS[j], Aq, b0h, b1h);
                MMA16816(sS[j], Aq, b0l, b1l);
                MMA16816(sS[j], Alr, b0h, b1h);
            }
        }

        // All warps done reading K -> overwrite K with K(kt+1), V into alt buf.
        __syncthreads();
        if (kt < qb) {
            load_k(kt + 1);
            load_v(kt + 1, 1 - vb);
            CP_COMMIT();
        }

        // ---- mask + scale ----
        const int qrow0 = q0 + w * 16 + gr;
#pragma unroll
        for (int j = 0; j < 8; j++) {
#pragma unroll
            for (int e = 0; e < 4; e++) {
                int kg = k0 + j * 8 + gc2 + (e & 1);
                int qg = qrow0 + (e >> 1) * 8;
                bool ok = (kg <= qg) && (kg + WIN > qg);
                sS[j][e] = ok ? sS[j][e] * 0.125f : -1e30f;
            }
        }
        // ---- online softmax (register-local; exp(-1e30-mn) == 0) ----
        float rmax0 = -1e30f, rmax1 = -1e30f;
#pragma unroll
        for (int j = 0; j < 8; j++) {
            rmax0 = fmaxf(rmax0, fmaxf(sS[j][0], sS[j][1]));
            rmax1 = fmaxf(rmax1, fmaxf(sS[j][2], sS[j][3]));
        }
        rmax0 = fmaxf(rmax0, __shfl_xor_sync(0xffffffffu, rmax0, 1));
        rmax0 = fmaxf(rmax0, __shfl_xor_sync(0xffffffffu, rmax0, 2));
        rmax1 = fmaxf(rmax1, __shfl_xor_sync(0xffffffffu, rmax1, 1));
        rmax1 = fmaxf(rmax1, __shfl_xor_sync(0xffffffffu, rmax1, 2));
        const float mn0 = fmaxf(m0_, rmax0), mn1 = fmaxf(m1_, rmax1);
        const float al0 = __expf(m0_ - mn0), al1 = __expf(m1_ - mn1);
        float ps0 = 0.f, ps1 = 0.f;
#pragma unroll
        for (int j = 0; j < 8; j++) {
            float p0 = __expf(sS[j][0] - mn0);
            float p1 = __expf(sS[j][1] - mn0);
            float p2 = __expf(sS[j][2] - mn1);
            float p3 = __expf(sS[j][3] - mn1);
            ps0 += p0 + p1; ps1 += p2 + p3;
            sS[j][0] = p0; sS[j][1] = p1; sS[j][2] = p2; sS[j][3] = p3;
        }
        ps0 += __shfl_xor_sync(0xffffffffu, ps0, 1);
        ps0 += __shfl_xor_sync(0xffffffffu, ps0, 2);
        ps1 += __shfl_xor_sync(0xffffffffu, ps1, 1);
        ps1 += __shfl_xor_sync(0xffffffffu, ps1, 2);
        l0 = l0 * al0 + ps0;
        l1 = l1 * al1 + ps1;
        m0_ = mn0; m1_ = mn1;
#pragma unroll
        for (int j = 0; j < 8; j++) {
            O[j][0] *= al0; O[j][1] *= al0;
            O[j][2] *= al1; O[j][3] *= al1;
        }

        // ---- O += P @ V (3-term), V[vb] resident ----
#pragma unroll
        for (int s = 0; s < 4; s++) {
            uint32_t pah[4], pal[4];
            split2(sS[2 * s][0], sS[2 * s][1], pah[0], pal[0]);
            split2(sS[2 * s][2], sS[2 * s][3], pah[1], pal[1]);
            split2(sS[2 * s + 1][0], sS[2 * s + 1][1], pah[2], pal[2]);
            split2(sS[2 * s + 1][2], sS[2 * s + 1][3], pah[3], pal[3]);

            uint32_t Vh4[4][4], Vl4[4][4];
            {
                int ksr = s * 16 + (lane & 7) + ((lane >> 3) & 1) * 8;
                uint32_t dby = ((lane >> 4) & 1) * 16;
#pragma unroll
                for (int dt = 0; dt < 4; dt++) {
                    LDSM_X4_T(Vh4[dt], sVh[vb] + ksr * ARS + dt * 32 + dby);
                    LDSM_X4_T(Vl4[dt], sVl[vb] + ksr * ARS + dt * 32 + dby);
                }
            }
#pragma unroll
            for (int j = 0; j < 8; j++) {
                uint32_t b0h = Vh4[j >> 1][(j & 1) * 2], b1h = Vh4[j >> 1][(j & 1) * 2 + 1];
                uint32_t b0l = Vl4[j >> 1][(j & 1) * 2], b1l = Vl4[j >> 1][(j & 1) * 2 + 1];
                MMA16816(O[j], pah, b0h, b1h);
                MMA16816(O[j], pah, b0l, b1l);
                MMA16816(O[j], pal, b0h, b1h);
            }
        }

        if (kt < qb) {
            CP_WAIT0();                 // K(kt+1)+V(kt+1) landed
            __syncthreads();
        }
    }

    // ---- finalize: write split bf16 mixed [MROWS, DMODEL] ----
    const float i0 = 1.f / l0, i1 = 1.f / l1;
    const size_t row0 = (size_t)b * SQ + q0 + w * 16 + gr;
    const int colb = h * HDIM + gc2;
#pragma unroll
    for (int j = 0; j < 8; j++) {
        uint32_t hh, ll;
        split2(O[j][0] * i0, O[j][1] * i0, hh, ll);
        *(uint32_t*)(mixHi + row0 * DMODEL + colb + j * 8) = hh;
        *(uint32_t*)(mixLo + row0 * DMODEL + colb + j * 8) = ll;
        split2(O[j][2] * i1, O[j][3] * i1, hh, ll);
        *(uint32_t*)(mixHi + (row0 + 8) * DMODEL + colb + j * 8) = hh;
        *(uint32_t*)(mixLo + (row0 + 8) * DMODEL + colb + j * 8) = ll;
    }
}

// ---------------------------------------------------------------------------
extern "C" void kernel_launch(void* const* d_in, const int* in_sizes, int n_in,
                              void* d_out, int out_size)
{
    const float* normed = (const float*)d_in[0];
    // d_in[1] = attn_mask: analytic (k<=q && k>=q-255), unused
    const float* Wqkv = (const float*)d_in[2];
    const float* bqkv = (const float*)d_in[3];
    const float* Wout = (const float*)d_in[4];
    const float* bout = (const float*)d_in[5];
    float* out = (float*)d_out;

    __nv_bfloat16 *aHi, *aLo, *w1Hi, *w1Lo, *w2Hi, *w2Lo, *qkvHi, *qkvLo;
    cudaGetSymbolAddress((void**)&aHi, g_aHi);
    cudaGetSymbolAddress((void**)&aLo, g_aLo);
    cudaGetSymbolAddress((void**)&w1Hi, g_w1Hi);
    cudaGetSymbolAddress((void**)&w1Lo, g_w1Lo);
    cudaGetSymbolAddress((void**)&w2Hi, g_w2Hi);
    cudaGetSymbolAddress((void**)&w2Lo, g_w2Lo);
    cudaGetSymbolAddress((void**)&qkvHi, g_qkvHi);
    cudaGetSymbolAddress((void**)&qkvLo, g_qkvLo);

    cudaFuncSetAttribute(gemm_mma_kernel,
                         cudaFuncAttributeMaxDynamicSharedMemorySize, GSMEM);
    cudaFuncSetAttribute(attn_mma_kernel,
                         cudaFuncAttributeMaxDynamicSharedMemorySize, ASMEM);

    // 1) split/convert normed + Wqkv
    conv_act_kernel<<<MROWS, 256>>>(normed, aHi, aLo);
    conv_w_kernel<<<dim3(3 * DMODEL / 32, KDIM / 32), dim3(32, 8)>>>(Wqkv, w1Hi, w1Lo, 3 * DMODEL);

    // 2) qkv GEMM -> split bf16 qkv directly
    gemm_mma_kernel<<<dim3(3 * DMODEL / 256, MROWS / 128), 256, GSMEM>>>(
        aHi, aLo, w1Hi, w1Lo, bqkv, nullptr, qkvHi, qkvLo, 3 * DMODEL);

    // 3) tensor-core local attention -> split bf16 mixed (into aHi/aLo)
    dim3 g2(SQ / 64, NHEAD, BATCH);
    attn_mma_kernel<<<g2, 128, ASMEM>>>(qkvHi, qkvLo, aHi, aLo);

    // 4) Wout conversion + out GEMM (fp32 out)
    conv_w_kernel<<<dim3(DMODEL / 32, KDIM / 32), dim3(32, 8)>>>(Wout, w2Hi, w2Lo, DMODEL);
    gemm_mma_kernel<<<dim3(DMODEL / 256, MROWS / 128), 256, GSMEM>>>(
        aHi, aLo, w2Hi, w2Lo, bout, out, nullptr, nullptr, DMODEL);
}